// round 5
// baseline (speedup 1.0000x reference)
#include <cuda_runtime.h>

#define TT 64
#define BB 1024
#define II 64
#define HH 256

// Scratch: hs[t][b][h] — first holds xW+biases, then overwritten in-place by the scan.
__device__ float g_hs[(size_t)TT * BB * HH];

// ---- f32x2 packed helpers (sm_103a FFMA2 path, PTX-only) --------------------
#define FMA_F32X2(d, a, b, c) \
    asm("fma.rn.f32x2 %0, %1, %2, %3;" : "=l"(d) : "l"(a), "l"(b), "l"(c))
#define PACK_F32X2(out, lo, hi) \
    asm("mov.b64 %0, {%1, %2};" : "=l"(out) : "f"(lo), "f"(hi))
#define UNPACK_F32X2(lo, hi, in) \
    asm("mov.b64 {%0, %1}, %2;" : "=f"(lo), "=f"(hi) : "l"(in))

// ---------------------------------------------------------------------------
// Kernel 1: g_hs[t,b,h] = data[t,b,:] . W_ih[h,:] + b_ih[h] + b_hh[h]
// ---------------------------------------------------------------------------
__global__ void __launch_bounds__(256) xw_kernel(
    const float* __restrict__ data,
    const float* __restrict__ W_ih,
    const float* __restrict__ b_ih,
    const float* __restrict__ b_hh)
{
    __shared__ float sX[256];  // 4 rows x 64 inputs
    const int tid = threadIdx.x;
    const long r0 = (long)blockIdx.x * 64;  // 64 (t,b)-rows per block

    float w[64];
    const float4* W4 = reinterpret_cast<const float4*>(W_ih) + tid * 16;
#pragma unroll
    for (int c = 0; c < 16; c++) {
        float4 v = W4[c];
        w[4*c+0] = v.x; w[4*c+1] = v.y; w[4*c+2] = v.z; w[4*c+3] = v.w;
    }
    const float bsum = b_ih[tid] + b_hh[tid];

    for (int rg = 0; rg < 16; rg++) {
        __syncthreads();
        sX[tid] = data[r0 * II + rg * 256 + tid];
        __syncthreads();
        float a0 = bsum, a1 = bsum, a2 = bsum, a3 = bsum;
        const float4* X4 = reinterpret_cast<const float4*>(sX);
#pragma unroll
        for (int c = 0; c < 16; c++) {
            float4 x;
            x = X4[c];      a0 += x.x*w[4*c] + x.y*w[4*c+1] + x.z*w[4*c+2] + x.w*w[4*c+3];
            x = X4[16+c];   a1 += x.x*w[4*c] + x.y*w[4*c+1] + x.z*w[4*c+2] + x.w*w[4*c+3];
            x = X4[32+c];   a2 += x.x*w[4*c] + x.y*w[4*c+1] + x.z*w[4*c+2] + x.w*w[4*c+3];
            x = X4[48+c];   a3 += x.x*w[4*c] + x.y*w[4*c+1] + x.z*w[4*c+2] + x.w*w[4*c+3];
        }
        long r = r0 + rg * 4;
        g_hs[(r+0)*HH + tid] = a0;
        g_hs[(r+1)*HH + tid] = a1;
        g_hs[(r+2)*HH + tid] = a2;
        g_hs[(r+3)*HH + tid] = a3;
    }
}

// ---------------------------------------------------------------------------
// Kernel 2: persistent RNN scan (unchanged — near FFMA floor).
// ---------------------------------------------------------------------------
__global__ void __launch_bounds__(512) rnn_scan_kernel(
    const float* __restrict__ h0_in, const float* __restrict__ W_hh)
{
    __shared__ float hp[2][8][256];
    const int tid = threadIdx.x;
    const int g = tid >> 8;
    const int h = tid & 255;
    const int b0 = blockIdx.x * 8;
    const int bg = g * 4;

    for (int m = tid; m < 2048; m += 512) {
        int bb = m >> 8, k = m & 255;
        hp[0][bb][k] = h0_in[(size_t)(b0 + bb) * HH + k];
    }
    __syncthreads();

    const float4* W4 = reinterpret_cast<const float4*>(W_hh + (size_t)h * HH);

    for (int t = 0; t < TT; t++) {
        float* hs_t = g_hs + (size_t)t * BB * HH;
        const int rb = t & 1;

        float acc[4];
#pragma unroll
        for (int b = 0; b < 4; b++)
            acc[b] = hs_t[(size_t)(b0 + bg + b) * HH + h];

        const float4* x0 = reinterpret_cast<const float4*>(&hp[rb][bg + 0][0]);
        const float4* x1 = reinterpret_cast<const float4*>(&hp[rb][bg + 1][0]);
        const float4* x2 = reinterpret_cast<const float4*>(&hp[rb][bg + 2][0]);
        const float4* x3 = reinterpret_cast<const float4*>(&hp[rb][bg + 3][0]);

#pragma unroll 8
        for (int k4 = 0; k4 < 64; k4++) {
            float4 w = W4[k4];
            float4 a = x0[k4];
            acc[0] += w.x*a.x + w.y*a.y + w.z*a.z + w.w*a.w;
            float4 b = x1[k4];
            acc[1] += w.x*b.x + w.y*b.y + w.z*b.z + w.w*b.w;
            float4 c = x2[k4];
            acc[2] += w.x*c.x + w.y*c.y + w.z*c.z + w.w*c.w;
            float4 d = x3[k4];
            acc[3] += w.x*d.x + w.y*d.y + w.z*d.z + w.w*d.w;
        }

#pragma unroll
        for (int b = 0; b < 4; b++) {
            float v = fmaxf(acc[b], 0.f);
            hs_t[(size_t)(b0 + bg + b) * HH + h] = v;
            hp[rb ^ 1][bg + b][h] = v;
        }
        __syncthreads();
    }
}

// ---------------------------------------------------------------------------
// Kernel 3: attention. Grid = 2048 (2 blocks per b; each handles 32 i-rows).
// 256 threads = 8 warps; warp w owns i-rows iwg..iwg+3 (4 per thread, packed
// in f32x2 pairs); lane owns the contiguous h-slice [lane*8, lane*8+8).
// Gather tile stored transposed Gs[n][h>>3][h&7] with 12-word padded rows ->
// conflict-free LDS.128, zero intra-warp duplication.
// Score partials reduced via smem transpose; softmax computed once (32 thr).
// ---------------------------------------------------------------------------
#define GROW 12                      // padded words per (n, hq) row
#define GN   (32 * GROW)             // 384 words per n
#define PROW 33                      // padded partial row

__global__ void __launch_bounds__(256, 2) attn_kernel(
    const int* __restrict__ nine_idx,
    const float* __restrict__ W_lin,
    const float* __restrict__ b_lin,
    float* __restrict__ out)
{
    extern __shared__ float sm[];
    float* Gs   = sm;                      // 2 * 9 * 384      = 6912
    float* Part = Gs + 2 * 9 * GN;         // 288 * 33         = 9504
    float* Ssum = Part + 288 * PROW;       // 288
    float* Psm  = Ssum + 288;              // 32 * 12          = 384
    float* sWl  = Psm + 32 * 12;           // 512
    int*   sidx = (int*)(sWl + 512);       // 9

    const int tid  = threadIdx.x;
    const int w    = tid >> 5;
    const int lane = tid & 31;
    const int b     = blockIdx.x >> 1;
    const int ibase = (blockIdx.x & 1) * 32;
    const int iwg   = ibase + w * 4;       // first global i of this warp
    const int hq = tid >> 3;               // gather store coords
    const int qs = tid & 7;

    if (tid < 9) sidx[tid] = nine_idx[b * 9 + tid];
    sWl[tid] = W_lin[tid];
    sWl[256 + tid] = W_lin[256 + tid];

    // hsr: 4 i-rows x 8 h, packed into i-pairs of f32x2
    unsigned long long hsr2[2][8];
#pragma unroll
    for (int p = 0; p < 2; p++) {
        const float* r0 = g_hs + ((size_t)(iwg + 2*p)     * BB + b) * HH + lane * 8;
        const float* r1 = g_hs + ((size_t)(iwg + 2*p + 1) * BB + b) * HH + lane * 8;
        float4 a0 = reinterpret_cast<const float4*>(r0)[0];
        float4 a1 = reinterpret_cast<const float4*>(r0)[1];
        float4 c0 = reinterpret_cast<const float4*>(r1)[0];
        float4 c1 = reinterpret_cast<const float4*>(r1)[1];
        PACK_F32X2(hsr2[p][0], a0.x, c0.x); PACK_F32X2(hsr2[p][1], a0.y, c0.y);
        PACK_F32X2(hsr2[p][2], a0.z, c0.z); PACK_F32X2(hsr2[p][3], a0.w, c0.w);
        PACK_F32X2(hsr2[p][4], a1.x, c1.x); PACK_F32X2(hsr2[p][5], a1.y, c1.y);
        PACK_F32X2(hsr2[p][6], a1.z, c1.z); PACK_F32X2(hsr2[p][7], a1.w, c1.w);
    }

    unsigned long long acc2[2][8];
#pragma unroll
    for (int p = 0; p < 2; p++)
#pragma unroll
        for (int e = 0; e < 8; e++) acc2[p][e] = 0ULL;

    const float bl = b_lin[0];
    __syncthreads();  // sidx ready

    // prefetch gather for j = 0 (thread tid covers h = tid for each n)
    float gr[9];
#pragma unroll
    for (int n = 0; n < 9; n++) {
        int iv = sidx[n];
        gr[n] = (iv < BB) ? g_hs[(size_t)iv * HH + tid] : 0.f;
    }

    float* out_attn = out + (size_t)TT * BB;

    for (int j = 0; j < TT; j++) {
        float* gbuf = Gs + (j & 1) * 9 * GN;
#pragma unroll
        for (int n = 0; n < 9; n++)
            gbuf[n * GN + hq * GROW + qs] = gr[n];
        __syncthreads();   // A: gather visible; prev-j context done

        if (j < TT - 1) {
            const float* src = g_hs + (size_t)(j + 1) * BB * HH;
#pragma unroll
            for (int n = 0; n < 9; n++) {
                int iv = sidx[n];
                gr[n] = (iv < BB) ? src[(size_t)iv * HH + tid] : 0.f;
            }
        }

        // ---- scores: s2[p][n] = sum_e (hsr pair) * g  (f32x2 packed) ----
        unsigned long long s2[2][9];
#pragma unroll
        for (int p = 0; p < 2; p++)
#pragma unroll
            for (int n = 0; n < 9; n++) s2[p][n] = 0ULL;

#pragma unroll
        for (int n = 0; n < 9; n++) {
            const float4* gp = reinterpret_cast<const float4*>(gbuf + n * GN + lane * GROW);
            float4 ga = gp[0];
            float4 gb = gp[1];
            float gv[8] = {ga.x, ga.y, ga.z, ga.w, gb.x, gb.y, gb.z, gb.w};
#pragma unroll
            for (int e = 0; e < 8; e++) {
                unsigned long long gd;
                PACK_F32X2(gd, gv[e], gv[e]);
                FMA_F32X2(s2[0][n], hsr2[0][e], gd, s2[0][n]);
                FMA_F32X2(s2[1][n], hsr2[1][e], gd, s2[1][n]);
            }
        }
        // write partials: Part[(iloc*9 + n)*33 + lane]
#pragma unroll
        for (int p = 0; p < 2; p++) {
#pragma unroll
            for (int n = 0; n < 9; n++) {
                float v0, v1;
                UNPACK_F32X2(v0, v1, s2[p][n]);
                int il = w * 4 + 2 * p;
                Part[(il * 9 + n) * PROW + lane] = v0;
                Part[((il + 1) * 9 + n) * PROW + lane] = v1;
            }
        }
        __syncthreads();   // B: partials ready

        // ---- tree-sum 288 rows of 32 ----
        {
            int pr = tid;
            const float* row = Part + pr * PROW;
            float t0 = 0.f, t1 = 0.f, t2 = 0.f, t3 = 0.f;
#pragma unroll
            for (int l = 0; l < 32; l += 4) {
                t0 += row[l]; t1 += row[l+1]; t2 += row[l+2]; t3 += row[l+3];
            }
            Ssum[pr] = (t0 + t1) + (t2 + t3);
            if (tid < 32) {
                pr = 256 + tid;
                const float* row2 = Part + pr * PROW;
                float u0 = 0.f, u1 = 0.f, u2 = 0.f, u3 = 0.f;
#pragma unroll
                for (int l = 0; l < 32; l += 4) {
                    u0 += row2[l]; u1 += row2[l+1]; u2 += row2[l+2]; u3 += row2[l+3];
                }
                Ssum[pr] = (u0 + u1) + (u2 + u3);
            }
        }
        __syncthreads();   // C: sums ready

        // ---- softmax (once, threads 0..31 = local i) + attn write ----
        if (tid < 32) {
            float s[9];
#pragma unroll
            for (int n = 0; n < 9; n++) s[n] = Ssum[tid * 9 + n];
            float m = s[0];
#pragma unroll
            for (int n = 1; n < 9; n++) m = fmaxf(m, s[n]);
            float sum = 0.f;
#pragma unroll
            for (int n = 0; n < 9; n++) { s[n] = __expf(s[n] - m); sum += s[n]; }
            float r = 1.f / sum;
            int gi = ibase + tid;
            size_t base = (((size_t)(gi * TT + j)) * BB + b) * 9;
#pragma unroll
            for (int n = 0; n < 9; n++) {
                float pv = s[n] * r;
                Psm[tid * 12 + n] = pv;
                out_attn[base + n] = pv;
            }
        }
        __syncthreads();   // D: p ready

        // ---- masked context: acc[i] += p[i] * g  (only j < i) ----
        if (j < iwg + 3) {
#pragma unroll
            for (int n = 0; n < 9; n++) {
                float p0 = (j < iwg)     ? Psm[(w*4 + 0) * 12 + n] : 0.f;
                float p1 = (j < iwg + 1) ? Psm[(w*4 + 1) * 12 + n] : 0.f;
                float p2 = (j < iwg + 2) ? Psm[(w*4 + 2) * 12 + n] : 0.f;
                float p3 = Psm[(w*4 + 3) * 12 + n];
                unsigned long long pp0, pp1;
                PACK_F32X2(pp0, p0, p1);
                PACK_F32X2(pp1, p2, p3);
                const float4* gp = reinterpret_cast<const float4*>(gbuf + n * GN + lane * GROW);
                float4 ga = gp[0];
                float4 gb = gp[1];
                float gv[8] = {ga.x, ga.y, ga.z, ga.w, gb.x, gb.y, gb.z, gb.w};
#pragma unroll
                for (int e = 0; e < 8; e++) {
                    unsigned long long gd;
                    PACK_F32X2(gd, gv[e], gv[e]);
                    FMA_F32X2(acc2[0][e], pp0, gd, acc2[0][e]);
                    FMA_F32X2(acc2[1][e], pp1, gd, acc2[1][e]);
                }
            }
        }
    }

    // ---- head: pred[i,b] = relu([c_i, hs_i] . W_lin + b_lin); c_0 = hs_0 ----
#pragma unroll
    for (int p = 0; p < 2; p++) {
#pragma unroll
        for (int k = 0; k < 2; k++) {
            int gi = iwg + 2 * p + k;
            float t = 0.f;
#pragma unroll
            for (int e = 0; e < 8; e++) {
                int h = lane * 8 + e;
                float hv0, hv1, av0, av1;
                UNPACK_F32X2(hv0, hv1, hsr2[p][e]);
                UNPACK_F32X2(av0, av1, acc2[p][e]);
                float hv = k ? hv1 : hv0;
                float av = k ? av1 : av0;
                float cv = (gi == 0) ? hv : av;
                t += cv * sWl[h] + hv * sWl[256 + h];
            }
            t += __shfl_xor_sync(0xffffffffu, t, 1);
            t += __shfl_xor_sync(0xffffffffu, t, 2);
            t += __shfl_xor_sync(0xffffffffu, t, 4);
            t += __shfl_xor_sync(0xffffffffu, t, 8);
            t += __shfl_xor_sync(0xffffffffu, t, 16);
            if (lane == 0)
                out[(size_t)gi * BB + b] = fmaxf(t + bl, 0.f);
        }
    }
}

// ---------------------------------------------------------------------------
extern "C" void kernel_launch(void* const* d_in, const int* in_sizes, int n_in,
                              void* d_out, int out_size)
{
    const float* data  = (const float*)d_in[0];
    const int*   nidx  = (const int*)d_in[1];
    /* d_in[2] = haven_flag (always 0, branch unused) */
    const float* h0    = (const float*)d_in[3];
    const float* W_ih  = (const float*)d_in[4];
    const float* W_hh  = (const float*)d_in[5];
    const float* b_ih  = (const float*)d_in[6];
    const float* b_hh  = (const float*)d_in[7];
    const float* W_lin = (const float*)d_in[8];
    const float* b_lin = (const float*)d_in[9];
    float* out = (float*)d_out;

    (void)in_sizes; (void)n_in; (void)out_size;

    xw_kernel<<<1024, 256>>>(data, W_ih, b_ih, b_hh);
    rnn_scan_kernel<<<128, 512>>>(h0, W_hh);

    const int attn_smem = (2 * 9 * GN + 288 * PROW + 288 + 32 * 12 + 512) * (int)sizeof(float)
                          + 16 * (int)sizeof(int);
    cudaFuncSetAttribute(attn_kernel,
                         cudaFuncAttributeMaxDynamicSharedMemorySize, attn_smem);
    attn_kernel<<<2048, 256, attn_smem>>>(nidx, W_lin, b_lin, out);
}

// round 6
// speedup vs baseline: 1.2372x; 1.2372x over previous
#include <cuda_runtime.h>

#define TT 64
#define BB 1024
#define II 64
#define HH 256

// Scratch: hs[t][b][h] — first holds xW+biases, then overwritten in-place by the scan.
__device__ float g_hs[(size_t)TT * BB * HH];

typedef unsigned long long u64;

// ---- f32x2 packed helpers (sm_103a FFMA2 path, PTX-only) --------------------
#define FMA_F32X2(d, a, b, c) \
    asm("fma.rn.f32x2 %0, %1, %2, %3;" : "=l"(d) : "l"(a), "l"(b), "l"(c))
#define PACK_F32X2(out, lo, hi) \
    asm("mov.b64 %0, {%1, %2};" : "=l"(out) : "f"(lo), "f"(hi))
#define UNPACK_F32X2(lo, hi, in) \
    asm("mov.b64 {%0, %1}, %2;" : "=f"(lo), "=f"(hi) : "l"(in))

// ---------------------------------------------------------------------------
// Kernel 1: g_hs[t,b,h] = data[t,b,:] . W_ih[h,:] + b_ih[h] + b_hh[h]
// ---------------------------------------------------------------------------
__global__ void __launch_bounds__(256) xw_kernel(
    const float* __restrict__ data,
    const float* __restrict__ W_ih,
    const float* __restrict__ b_ih,
    const float* __restrict__ b_hh)
{
    __shared__ float sX[256];
    const int tid = threadIdx.x;
    const long r0 = (long)blockIdx.x * 64;

    float w[64];
    const float4* W4 = reinterpret_cast<const float4*>(W_ih) + tid * 16;
#pragma unroll
    for (int c = 0; c < 16; c++) {
        float4 v = W4[c];
        w[4*c+0] = v.x; w[4*c+1] = v.y; w[4*c+2] = v.z; w[4*c+3] = v.w;
    }
    const float bsum = b_ih[tid] + b_hh[tid];

    for (int rg = 0; rg < 16; rg++) {
        __syncthreads();
        sX[tid] = data[r0 * II + rg * 256 + tid];
        __syncthreads();
        float a0 = bsum, a1 = bsum, a2 = bsum, a3 = bsum;
        const float4* X4 = reinterpret_cast<const float4*>(sX);
#pragma unroll
        for (int c = 0; c < 16; c++) {
            float4 x;
            x = X4[c];      a0 += x.x*w[4*c] + x.y*w[4*c+1] + x.z*w[4*c+2] + x.w*w[4*c+3];
            x = X4[16+c];   a1 += x.x*w[4*c] + x.y*w[4*c+1] + x.z*w[4*c+2] + x.w*w[4*c+3];
            x = X4[32+c];   a2 += x.x*w[4*c] + x.y*w[4*c+1] + x.z*w[4*c+2] + x.w*w[4*c+3];
            x = X4[48+c];   a3 += x.x*w[4*c] + x.y*w[4*c+1] + x.z*w[4*c+2] + x.w*w[4*c+3];
        }
        long r = r0 + rg * 4;
        g_hs[(r+0)*HH + tid] = a0;
        g_hs[(r+1)*HH + tid] = a1;
        g_hs[(r+2)*HH + tid] = a2;
        g_hs[(r+3)*HH + tid] = a3;
    }
}

// ---------------------------------------------------------------------------
// Kernel 2: persistent RNN scan (unchanged — near its floor).
// ---------------------------------------------------------------------------
__global__ void __launch_bounds__(512) rnn_scan_kernel(
    const float* __restrict__ h0_in, const float* __restrict__ W_hh)
{
    __shared__ float hp[2][8][256];
    const int tid = threadIdx.x;
    const int g = tid >> 8;
    const int h = tid & 255;
    const int b0 = blockIdx.x * 8;
    const int bg = g * 4;

    for (int m = tid; m < 2048; m += 512) {
        int bb = m >> 8, k = m & 255;
        hp[0][bb][k] = h0_in[(size_t)(b0 + bb) * HH + k];
    }
    __syncthreads();

    const float4* W4 = reinterpret_cast<const float4*>(W_hh + (size_t)h * HH);

    for (int t = 0; t < TT; t++) {
        float* hs_t = g_hs + (size_t)t * BB * HH;
        const int rb = t & 1;

        float acc[4];
#pragma unroll
        for (int b = 0; b < 4; b++)
            acc[b] = hs_t[(size_t)(b0 + bg + b) * HH + h];

        const float4* x0 = reinterpret_cast<const float4*>(&hp[rb][bg + 0][0]);
        const float4* x1 = reinterpret_cast<const float4*>(&hp[rb][bg + 1][0]);
        const float4* x2 = reinterpret_cast<const float4*>(&hp[rb][bg + 2][0]);
        const float4* x3 = reinterpret_cast<const float4*>(&hp[rb][bg + 3][0]);

#pragma unroll 8
        for (int k4 = 0; k4 < 64; k4++) {
            float4 w = W4[k4];
            float4 a = x0[k4];
            acc[0] += w.x*a.x + w.y*a.y + w.z*a.z + w.w*a.w;
            float4 b = x1[k4];
            acc[1] += w.x*b.x + w.y*b.y + w.z*b.z + w.w*b.w;
            float4 c = x2[k4];
            acc[2] += w.x*c.x + w.y*c.y + w.z*c.z + w.w*c.w;
            float4 d = x3[k4];
            acc[3] += w.x*d.x + w.y*d.y + w.z*d.z + w.w*d.w;
        }

#pragma unroll
        for (int b = 0; b < 4; b++) {
            float v = fmaxf(acc[b], 0.f);
            hs_t[(size_t)(b0 + bg + b) * HH + h] = v;
            hp[rb ^ 1][bg + b][h] = v;
        }
        __syncthreads();
    }
}

// ---------------------------------------------------------------------------
// Kernel 3: attention. Grid = 2048 (2 blocks per b, 32 i-rows each).
// 256 threads: tid = iq*16 + hq (iq 0..15, hq 0..15). Thread owns i-pair
// (iA = ibase+2*iq, iB = iA+1).
//   scores : h-slice {hq+16e}, n-pair FMA2 with natural LDS.64 gather pairs
//   context: h-chunks {4hq+64c+e}, LDS.128 gather, h-pair FMA2 accumulators
// Gather staged in BOTH layouts (n-contig Gsn, h-contig Gsh), double-buffered;
// register prefetch of next j -> ONE barrier per j. Softmax in registers.
// ---------------------------------------------------------------------------
#define GSN_STRIDE 10      // 9 n + 1 pad (words)  -> conflict-free LDS.64
#define GSH_STRIDE 264     // 256 h + 8 pad (words)

__global__ void __launch_bounds__(256, 2) attn_kernel(
    const int* __restrict__ nine_idx,
    const float* __restrict__ W_lin,
    const float* __restrict__ b_lin,
    float* __restrict__ out)
{
    __shared__ float Gsn[2][256 * GSN_STRIDE];
    __shared__ float Gsh[2][9 * GSH_STRIDE];
    __shared__ float sWl[512];
    __shared__ int   sidx[9];

    const int tid   = threadIdx.x;
    const int b     = blockIdx.x >> 1;
    const int ibase = (blockIdx.x & 1) * 32;
    const int iq    = tid >> 4;
    const int hq    = tid & 15;
    const int iA    = ibase + 2 * iq;
    const int iB    = iA + 1;

    if (tid < 9) sidx[tid] = nine_idx[b * 9 + tid];
    sWl[tid] = W_lin[tid];
    sWl[256 + tid] = W_lin[256 + tid];
    __syncthreads();

    int idxr[9];
#pragma unroll
    for (int n = 0; n < 9; n++) idxr[n] = sidx[n];

    // H rows for the scores phase (strided h = hq + 16e)
    float hsA[16], hsB[16];
    {
        const float* HA = g_hs + ((size_t)iA * BB + b) * HH + hq;
        const float* HB = g_hs + ((size_t)iB * BB + b) * HH + hq;
#pragma unroll
        for (int e = 0; e < 16; e++) { hsA[e] = HA[16 * e]; hsB[e] = HB[16 * e]; }
    }

    // context accumulators: [i][chunk][h-pair], f32x2 packed over h
    u64 acc2[2][4][2];
#pragma unroll
    for (int i = 0; i < 2; i++)
#pragma unroll
        for (int c = 0; c < 4; c++) { acc2[i][c][0] = 0ULL; acc2[i][c][1] = 0ULL; }

    const float bl = b_lin[0];

    // prefetch gather rows for j = 0 (thread covers h = tid... here h = tid&255 = tid)
    float gr[9];
#pragma unroll
    for (int n = 0; n < 9; n++) {
        int iv = idxr[n];
        gr[n] = (iv < BB) ? g_hs[(size_t)iv * HH + tid] : 0.f;
    }

    float* out_attn = out + (size_t)TT * BB;

    for (int j = 0; j < TT; j++) {
        float* gn = Gsn[j & 1];
        float* gh = Gsh[j & 1];
#pragma unroll
        for (int n = 0; n < 9; n++) gn[tid * GSN_STRIDE + n] = gr[n];
#pragma unroll
        for (int n = 0; n < 9; n++) gh[n * GSH_STRIDE + tid] = gr[n];
        __syncthreads();   // single barrier per j

        if (j < TT - 1) {
            const float* src = g_hs + (size_t)(j + 1) * BB * HH;
#pragma unroll
            for (int n = 0; n < 9; n++) {
                int iv = idxr[n];
                gr[n] = (iv < BB) ? src[(size_t)iv * HH + tid] : 0.f;
            }
        }

        // ---- scores: n-pair packed FMA2, LDS.64 gather pairs ----
        u64 s2A[4], s2B[4];
        float s8A = 0.f, s8B = 0.f;
#pragma unroll
        for (int p = 0; p < 4; p++) { s2A[p] = 0ULL; s2B[p] = 0ULL; }

#pragma unroll
        for (int e = 0; e < 16; e++) {
            const float* base = gn + (hq + 16 * e) * GSN_STRIDE;
            u64 g01 = *reinterpret_cast<const u64*>(base);
            u64 g23 = *reinterpret_cast<const u64*>(base + 2);
            u64 g45 = *reinterpret_cast<const u64*>(base + 4);
            u64 g67 = *reinterpret_cast<const u64*>(base + 6);
            float g8v = base[8];
            float xA = hsA[e], xB = hsB[e];
            u64 xdA, xdB;
            PACK_F32X2(xdA, xA, xA);
            PACK_F32X2(xdB, xB, xB);
            FMA_F32X2(s2A[0], g01, xdA, s2A[0]);
            FMA_F32X2(s2A[1], g23, xdA, s2A[1]);
            FMA_F32X2(s2A[2], g45, xdA, s2A[2]);
            FMA_F32X2(s2A[3], g67, xdA, s2A[3]);
            FMA_F32X2(s2B[0], g01, xdB, s2B[0]);
            FMA_F32X2(s2B[1], g23, xdB, s2B[1]);
            FMA_F32X2(s2B[2], g45, xdB, s2B[2]);
            FMA_F32X2(s2B[3], g67, xdB, s2B[3]);
            s8A += xA * g8v;
            s8B += xB * g8v;
        }

        float pA[9], pB[9];
#pragma unroll
        for (int p = 0; p < 4; p++) {
            UNPACK_F32X2(pA[2*p], pA[2*p+1], s2A[p]);
            UNPACK_F32X2(pB[2*p], pB[2*p+1], s2B[p]);
        }
        pA[8] = s8A; pB[8] = s8B;

        // reduce the 16 hq-partials (lane bits 0..3)
#pragma unroll
        for (int n = 0; n < 9; n++) {
            float vA = pA[n], vB = pB[n];
            vA += __shfl_xor_sync(0xffffffffu, vA, 1);
            vA += __shfl_xor_sync(0xffffffffu, vA, 2);
            vA += __shfl_xor_sync(0xffffffffu, vA, 4);
            vA += __shfl_xor_sync(0xffffffffu, vA, 8);
            vB += __shfl_xor_sync(0xffffffffu, vB, 1);
            vB += __shfl_xor_sync(0xffffffffu, vB, 2);
            vB += __shfl_xor_sync(0xffffffffu, vB, 4);
            vB += __shfl_xor_sync(0xffffffffu, vB, 8);
            pA[n] = vA; pB[n] = vB;
        }

        // softmax over n (redundant across the 16 hq lanes)
        {
            float mA = pA[0], mB = pB[0];
#pragma unroll
            for (int n = 1; n < 9; n++) { mA = fmaxf(mA, pA[n]); mB = fmaxf(mB, pB[n]); }
            float sumA = 0.f, sumB = 0.f;
#pragma unroll
            for (int n = 0; n < 9; n++) {
                pA[n] = __expf(pA[n] - mA); sumA += pA[n];
                pB[n] = __expf(pB[n] - mB); sumB += pB[n];
            }
            float rA = 1.f / sumA, rB = 1.f / sumB;
#pragma unroll
            for (int n = 0; n < 9; n++) { pA[n] *= rA; pB[n] *= rB; }
        }

        // attn output (lanes hq<9 write one n for both i)
        if (hq < 9) {
            out_attn[(((size_t)(iA * TT + j)) * BB + b) * 9 + hq] = pA[hq];
            out_attn[(((size_t)(iB * TT + j)) * BB + b) * 9 + hq] = pB[hq];
        }

        // ---- masked context: LDS.128 gather, h-pair packed FMA2 ----
        if (j < iB) {
            const bool dA = (j < iA);
#pragma unroll
            for (int n = 0; n < 9; n++) {
                float vA = dA ? pA[n] : 0.f;
                u64 pdA, pdB;
                PACK_F32X2(pdA, vA, vA);
                PACK_F32X2(pdB, pB[n], pB[n]);
                const float* rowp = gh + n * GSH_STRIDE + 4 * hq;
#pragma unroll
                for (int c = 0; c < 4; c++) {
                    ulonglong2 gv = *reinterpret_cast<const ulonglong2*>(rowp + 64 * c);
                    FMA_F32X2(acc2[0][c][0], pdA, gv.x, acc2[0][c][0]);
                    FMA_F32X2(acc2[0][c][1], pdA, gv.y, acc2[0][c][1]);
                    FMA_F32X2(acc2[1][c][0], pdB, gv.x, acc2[1][c][0]);
                    FMA_F32X2(acc2[1][c][1], pdB, gv.y, acc2[1][c][1]);
                }
            }
        }
    }

    // ---- head: pred[i,b] = relu([c_i, hs_i] . W_lin + b_lin); c_0 = hs_0 ----
#pragma unroll
    for (int i = 0; i < 2; i++) {
        const int gi = (i == 0) ? iA : iB;
        const float* hrow = g_hs + ((size_t)gi * BB + b) * HH;
        float t = 0.f;
#pragma unroll
        for (int c = 0; c < 4; c++) {
            const int h0 = 4 * hq + 64 * c;
            float4 hv = *reinterpret_cast<const float4*>(hrow + h0);
            float a0, a1, a2, a3;
            UNPACK_F32X2(a0, a1, acc2[i][c][0]);
            UNPACK_F32X2(a2, a3, acc2[i][c][1]);
            if (gi == 0) { a0 = hv.x; a1 = hv.y; a2 = hv.z; a3 = hv.w; }
            t += a0 * sWl[h0]   + hv.x * sWl[256 + h0];
            t += a1 * sWl[h0+1] + hv.y * sWl[256 + h0 + 1];
            t += a2 * sWl[h0+2] + hv.z * sWl[256 + h0 + 2];
            t += a3 * sWl[h0+3] + hv.w * sWl[256 + h0 + 3];
        }
        t += __shfl_xor_sync(0xffffffffu, t, 1);
        t += __shfl_xor_sync(0xffffffffu, t, 2);
        t += __shfl_xor_sync(0xffffffffu, t, 4);
        t += __shfl_xor_sync(0xffffffffu, t, 8);
        if (hq == 0)
            out[(size_t)gi * BB + b] = fmaxf(t + bl, 0.f);
    }
}

// ---------------------------------------------------------------------------
extern "C" void kernel_launch(void* const* d_in, const int* in_sizes, int n_in,
                              void* d_out, int out_size)
{
    const float* data  = (const float*)d_in[0];
    const int*   nidx  = (const int*)d_in[1];
    /* d_in[2] = haven_flag (always 0, branch unused) */
    const float* h0    = (const float*)d_in[3];
    const float* W_ih  = (const float*)d_in[4];
    const float* W_hh  = (const float*)d_in[5];
    const float* b_ih  = (const float*)d_in[6];
    const float* b_hh  = (const float*)d_in[7];
    const float* W_lin = (const float*)d_in[8];
    const float* b_lin = (const float*)d_in[9];
    float* out = (float*)d_out;

    (void)in_sizes; (void)n_in; (void)out_size;

    xw_kernel<<<1024, 256>>>(data, W_ih, b_ih, b_hh);
    rnn_scan_kernel<<<128, 512>>>(h0, W_hh);
    attn_kernel<<<2048, 256>>>(nidx, W_lin, b_lin, out);
}

// round 7
// speedup vs baseline: 1.4637x; 1.1830x over previous
#include <cuda_runtime.h>

#define TT 64
#define BB 1024
#define II 64
#define HH 256

// Scratch: hs[t][b][h] — first holds xW+biases, then overwritten in-place by the scan.
__device__ float g_hs[(size_t)TT * BB * HH];
// W_hh transposed: WT[k][h] = W_hh[h][k]  (coalesced RNN reads)
__device__ float g_WT[HH * HH];

typedef unsigned long long u64;

// ---- f32x2 packed helpers (sm_103a FFMA2 path, PTX-only) --------------------
#define FMA_F32X2(d, a, b, c) \
    asm("fma.rn.f32x2 %0, %1, %2, %3;" : "=l"(d) : "l"(a), "l"(b), "l"(c))
#define PACK_F32X2(out, lo, hi) \
    asm("mov.b64 %0, {%1, %2};" : "=l"(out) : "f"(lo), "f"(hi))
#define UNPACK_F32X2(lo, hi, in) \
    asm("mov.b64 {%0, %1}, %2;" : "=f"(lo), "=f"(hi) : "l"(in))

// ---------------------------------------------------------------------------
// Kernel 0: transpose W_hh (one-time, 256 KB)
// ---------------------------------------------------------------------------
__global__ void __launch_bounds__(256) wt_kernel(const float* __restrict__ W_hh)
{
    const int k = blockIdx.x;
    const int h = threadIdx.x;
    g_WT[k * HH + h] = W_hh[h * HH + k];
}

// ---------------------------------------------------------------------------
// Kernel 1: g_hs[t,b,h] = data[t,b,:] . W_ih[h,:] + b_ih[h] + b_hh[h]
// ---------------------------------------------------------------------------
__global__ void __launch_bounds__(256) xw_kernel(
    const float* __restrict__ data,
    const float* __restrict__ W_ih,
    const float* __restrict__ b_ih,
    const float* __restrict__ b_hh)
{
    __shared__ float sX[256];
    const int tid = threadIdx.x;
    const long r0 = (long)blockIdx.x * 64;

    float w[64];
    const float4* W4 = reinterpret_cast<const float4*>(W_ih) + tid * 16;
#pragma unroll
    for (int c = 0; c < 16; c++) {
        float4 v = W4[c];
        w[4*c+0] = v.x; w[4*c+1] = v.y; w[4*c+2] = v.z; w[4*c+3] = v.w;
    }
    const float bsum = b_ih[tid] + b_hh[tid];

    for (int rg = 0; rg < 16; rg++) {
        __syncthreads();
        sX[tid] = data[r0 * II + rg * 256 + tid];
        __syncthreads();
        float a0 = bsum, a1 = bsum, a2 = bsum, a3 = bsum;
        const float4* X4 = reinterpret_cast<const float4*>(sX);
#pragma unroll
        for (int c = 0; c < 16; c++) {
            float4 x;
            x = X4[c];      a0 += x.x*w[4*c] + x.y*w[4*c+1] + x.z*w[4*c+2] + x.w*w[4*c+3];
            x = X4[16+c];   a1 += x.x*w[4*c] + x.y*w[4*c+1] + x.z*w[4*c+2] + x.w*w[4*c+3];
            x = X4[32+c];   a2 += x.x*w[4*c] + x.y*w[4*c+1] + x.z*w[4*c+2] + x.w*w[4*c+3];
            x = X4[48+c];   a3 += x.x*w[4*c] + x.y*w[4*c+1] + x.z*w[4*c+2] + x.w*w[4*c+3];
        }
        long r = r0 + rg * 4;
        g_hs[(r+0)*HH + tid] = a0;
        g_hs[(r+1)*HH + tid] = a1;
        g_hs[(r+2)*HH + tid] = a2;
        g_hs[(r+3)*HH + tid] = a3;
    }
}

// ---------------------------------------------------------------------------
// Kernel 2: persistent RNN scan, transposed-W orientation.
// 128 blocks x 512 threads; block owns 8 batches for all 64 steps.
// Thread (bq = tid>>6, hw = tid&63): 1 batch x 4 contiguous h (h = hw*4..+3).
// Per k: WT[k][h4] via coalesced LDG.128 (lanes = consecutive float4s),
// hp[bq][k] smem broadcast, 2x FMA_F32X2. L2 serves WT (chip-resident).
// ---------------------------------------------------------------------------
__global__ void __launch_bounds__(512) rnn_scan_kernel(
    const float* __restrict__ h0_in)
{
    __shared__ float hp[2][8][260];
    const int tid = threadIdx.x;
    const int bq = tid >> 6;      // 0..7 : batch within block
    const int hw = tid & 63;      // 0..63: float4 index over h
    const int b0 = blockIdx.x * 8;
    const int bglob = b0 + bq;

    for (int m = tid; m < 2048; m += 512) {
        int bb = m >> 8, k = m & 255;
        hp[0][bb][k] = h0_in[(size_t)(b0 + bb) * HH + k];
    }
    __syncthreads();

    const ulonglong2* WT2 = reinterpret_cast<const ulonglong2*>(g_WT);

    for (int t = 0; t < TT; t++) {
        float* hs_row = g_hs + (size_t)t * BB * HH + (size_t)bglob * HH + hw * 4;
        const int rb = t & 1;

        // acc over 4 h, packed as 2 f32x2
        float4 a0 = *reinterpret_cast<const float4*>(hs_row);
        u64 acc2[2];
        PACK_F32X2(acc2[0], a0.x, a0.y);
        PACK_F32X2(acc2[1], a0.z, a0.w);

        const float4* hp4 = reinterpret_cast<const float4*>(&hp[rb][bq][0]);

#pragma unroll 8
        for (int k4 = 0; k4 < 64; k4++) {
            float4 hv = hp4[k4];                       // broadcast LDS.128
            const ulonglong2* wr = WT2 + (size_t)(k4 * 4) * 64 + hw;
            ulonglong2 w0 = wr[0];                     // WT[4k4+0][h4]
            ulonglong2 w1 = wr[64];                    // WT[4k4+1][h4]
            ulonglong2 w2 = wr[128];
            ulonglong2 w3 = wr[192];
            u64 hd;
            PACK_F32X2(hd, hv.x, hv.x);
            FMA_F32X2(acc2[0], w0.x, hd, acc2[0]);
            FMA_F32X2(acc2[1], w0.y, hd, acc2[1]);
            PACK_F32X2(hd, hv.y, hv.y);
            FMA_F32X2(acc2[0], w1.x, hd, acc2[0]);
            FMA_F32X2(acc2[1], w1.y, hd, acc2[1]);
            PACK_F32X2(hd, hv.z, hv.z);
            FMA_F32X2(acc2[0], w2.x, hd, acc2[0]);
            FMA_F32X2(acc2[1], w2.y, hd, acc2[1]);
            PACK_F32X2(hd, hv.w, hv.w);
            FMA_F32X2(acc2[0], w3.x, hd, acc2[0]);
            FMA_F32X2(acc2[1], w3.y, hd, acc2[1]);
        }

        float v0, v1, v2, v3;
        UNPACK_F32X2(v0, v1, acc2[0]);
        UNPACK_F32X2(v2, v3, acc2[1]);
        v0 = fmaxf(v0, 0.f); v1 = fmaxf(v1, 0.f);
        v2 = fmaxf(v2, 0.f); v3 = fmaxf(v3, 0.f);
        float4 vv = make_float4(v0, v1, v2, v3);
        *reinterpret_cast<float4*>(hs_row) = vv;
        *reinterpret_cast<float4*>(&hp[rb ^ 1][bq][hw * 4]) = vv;
        __syncthreads();
    }
}

// ---------------------------------------------------------------------------
// Kernel 3: attention (round-6 structure, unchanged).
// ---------------------------------------------------------------------------
#define GSN_STRIDE 10      // 9 n + 1 pad (words)  -> conflict-free LDS.64
#define GSH_STRIDE 264     // 256 h + 8 pad (words)

__global__ void __launch_bounds__(256, 2) attn_kernel(
    const int* __restrict__ nine_idx,
    const float* __restrict__ W_lin,
    const float* __restrict__ b_lin,
    float* __restrict__ out)
{
    __shared__ float Gsn[2][256 * GSN_STRIDE];
    __shared__ float Gsh[2][9 * GSH_STRIDE];
    __shared__ float sWl[512];
    __shared__ int   sidx[9];

    const int tid   = threadIdx.x;
    const int b     = blockIdx.x >> 1;
    const int ibase = (blockIdx.x & 1) * 32;
    const int iq    = tid >> 4;
    const int hq    = tid & 15;
    const int iA    = ibase + 2 * iq;
    const int iB    = iA + 1;

    if (tid < 9) sidx[tid] = nine_idx[b * 9 + tid];
    sWl[tid] = W_lin[tid];
    sWl[256 + tid] = W_lin[256 + tid];
    __syncthreads();

    int idxr[9];
#pragma unroll
    for (int n = 0; n < 9; n++) idxr[n] = sidx[n];

    float hsA[16], hsB[16];
    {
        const float* HA = g_hs + ((size_t)iA * BB + b) * HH + hq;
        const float* HB = g_hs + ((size_t)iB * BB + b) * HH + hq;
#pragma unroll
        for (int e = 0; e < 16; e++) { hsA[e] = HA[16 * e]; hsB[e] = HB[16 * e]; }
    }

    u64 acc2[2][4][2];
#pragma unroll
    for (int i = 0; i < 2; i++)
#pragma unroll
        for (int c = 0; c < 4; c++) { acc2[i][c][0] = 0ULL; acc2[i][c][1] = 0ULL; }

    const float bl = b_lin[0];

    float gr[9];
#pragma unroll
    for (int n = 0; n < 9; n++) {
        int iv = idxr[n];
        gr[n] = (iv < BB) ? g_hs[(size_t)iv * HH + tid] : 0.f;
    }

    float* out_attn = out + (size_t)TT * BB;

    for (int j = 0; j < TT; j++) {
        float* gn = Gsn[j & 1];
        float* gh = Gsh[j & 1];
#pragma unroll
        for (int n = 0; n < 9; n++) gn[tid * GSN_STRIDE + n] = gr[n];
#pragma unroll
        for (int n = 0; n < 9; n++) gh[n * GSH_STRIDE + tid] = gr[n];
        __syncthreads();

        if (j < TT - 1) {
            const float* src = g_hs + (size_t)(j + 1) * BB * HH;
#pragma unroll
            for (int n = 0; n < 9; n++) {
                int iv = idxr[n];
                gr[n] = (iv < BB) ? src[(size_t)iv * HH + tid] : 0.f;
            }
        }

        u64 s2A[4], s2B[4];
        float s8A = 0.f, s8B = 0.f;
#pragma unroll
        for (int p = 0; p < 4; p++) { s2A[p] = 0ULL; s2B[p] = 0ULL; }

#pragma unroll
        for (int e = 0; e < 16; e++) {
            const float* base = gn + (hq + 16 * e) * GSN_STRIDE;
            u64 g01 = *reinterpret_cast<const u64*>(base);
            u64 g23 = *reinterpret_cast<const u64*>(base + 2);
            u64 g45 = *reinterpret_cast<const u64*>(base + 4);
            u64 g67 = *reinterpret_cast<const u64*>(base + 6);
            float g8v = base[8];
            float xA = hsA[e], xB = hsB[e];
            u64 xdA, xdB;
            PACK_F32X2(xdA, xA, xA);
            PACK_F32X2(xdB, xB, xB);
            FMA_F32X2(s2A[0], g01, xdA, s2A[0]);
            FMA_F32X2(s2A[1], g23, xdA, s2A[1]);
            FMA_F32X2(s2A[2], g45, xdA, s2A[2]);
            FMA_F32X2(s2A[3], g67, xdA, s2A[3]);
            FMA_F32X2(s2B[0], g01, xdB, s2B[0]);
            FMA_F32X2(s2B[1], g23, xdB, s2B[1]);
            FMA_F32X2(s2B[2], g45, xdB, s2B[2]);
            FMA_F32X2(s2B[3], g67, xdB, s2B[3]);
            s8A += xA * g8v;
            s8B += xB * g8v;
        }

        float pA[9], pB[9];
#pragma unroll
        for (int p = 0; p < 4; p++) {
            UNPACK_F32X2(pA[2*p], pA[2*p+1], s2A[p]);
            UNPACK_F32X2(pB[2*p], pB[2*p+1], s2B[p]);
        }
        pA[8] = s8A; pB[8] = s8B;

#pragma unroll
        for (int n = 0; n < 9; n++) {
            float vA = pA[n], vB = pB[n];
            vA += __shfl_xor_sync(0xffffffffu, vA, 1);
            vA += __shfl_xor_sync(0xffffffffu, vA, 2);
            vA += __shfl_xor_sync(0xffffffffu, vA, 4);
            vA += __shfl_xor_sync(0xffffffffu, vA, 8);
            vB += __shfl_xor_sync(0xffffffffu, vB, 1);
            vB += __shfl_xor_sync(0xffffffffu, vB, 2);
            vB += __shfl_xor_sync(0xffffffffu, vB, 4);
            vB += __shfl_xor_sync(0xffffffffu, vB, 8);
            pA[n] = vA; pB[n] = vB;
        }

        {
            float mA = pA[0], mB = pB[0];
#pragma unroll
            for (int n = 1; n < 9; n++) { mA = fmaxf(mA, pA[n]); mB = fmaxf(mB, pB[n]); }
            float sumA = 0.f, sumB = 0.f;
#pragma unroll
            for (int n = 0; n < 9; n++) {
                pA[n] = __expf(pA[n] - mA); sumA += pA[n];
                pB[n] = __expf(pB[n] - mB); sumB += pB[n];
            }
            float rA = 1.f / sumA, rB = 1.f / sumB;
#pragma unroll
            for (int n = 0; n < 9; n++) { pA[n] *= rA; pB[n] *= rB; }
        }

        if (hq < 9) {
            out_attn[(((size_t)(iA * TT + j)) * BB + b) * 9 + hq] = pA[hq];
            out_attn[(((size_t)(iB * TT + j)) * BB + b) * 9 + hq] = pB[hq];
        }

        if (j < iB) {
            const bool dA = (j < iA);
#pragma unroll
            for (int n = 0; n < 9; n++) {
                float vA = dA ? pA[n] : 0.f;
                u64 pdA, pdB;
                PACK_F32X2(pdA, vA, vA);
                PACK_F32X2(pdB, pB[n], pB[n]);
                const float* rowp = gh + n * GSH_STRIDE + 4 * hq;
#pragma unroll
                for (int c = 0; c < 4; c++) {
                    ulonglong2 gv = *reinterpret_cast<const ulonglong2*>(rowp + 64 * c);
                    FMA_F32X2(acc2[0][c][0], pdA, gv.x, acc2[0][c][0]);
                    FMA_F32X2(acc2[0][c][1], pdA, gv.y, acc2[0][c][1]);
                    FMA_F32X2(acc2[1][c][0], pdB, gv.x, acc2[1][c][0]);
                    FMA_F32X2(acc2[1][c][1], pdB, gv.y, acc2[1][c][1]);
                }
            }
        }
    }

#pragma unroll
    for (int i = 0; i < 2; i++) {
        const int gi = (i == 0) ? iA : iB;
        const float* hrow = g_hs + ((size_t)gi * BB + b) * HH;
        float t = 0.f;
#pragma unroll
        for (int c = 0; c < 4; c++) {
            const int h0 = 4 * hq + 64 * c;
            float4 hv = *reinterpret_cast<const float4*>(hrow + h0);
            float a0, a1, a2, a3;
            UNPACK_F32X2(a0, a1, acc2[i][c][0]);
            UNPACK_F32X2(a2, a3, acc2[i][c][1]);
            if (gi == 0) { a0 = hv.x; a1 = hv.y; a2 = hv.z; a3 = hv.w; }
            t += a0 * sWl[h0]   + hv.x * sWl[256 + h0];
            t += a1 * sWl[h0+1] + hv.y * sWl[256 + h0 + 1];
            t += a2 * sWl[h0+2] + hv.z * sWl[256 + h0 + 2];
            t += a3 * sWl[h0+3] + hv.w * sWl[256 + h0 + 3];
        }
        t += __shfl_xor_sync(0xffffffffu, t, 1);
        t += __shfl_xor_sync(0xffffffffu, t, 2);
        t += __shfl_xor_sync(0xffffffffu, t, 4);
        t += __shfl_xor_sync(0xffffffffu, t, 8);
        if (hq == 0)
            out[(size_t)gi * BB + b] = fmaxf(t + bl, 0.f);
    }
}

// ---------------------------------------------------------------------------
extern "C" void kernel_launch(void* const* d_in, const int* in_sizes, int n_in,
                              void* d_out, int out_size)
{
    const float* data  = (const float*)d_in[0];
    const int*   nidx  = (const int*)d_in[1];
    /* d_in[2] = haven_flag (always 0, branch unused) */
    const float* h0    = (const float*)d_in[3];
    const float* W_ih  = (const float*)d_in[4];
    const float* W_hh  = (const float*)d_in[5];
    const float* b_ih  = (const float*)d_in[6];
    const float* b_hh  = (const float*)d_in[7];
    const float* W_lin = (const float*)d_in[8];
    const float* b_lin = (const float*)d_in[9];
    float* out = (float*)d_out;

    (void)in_sizes; (void)n_in; (void)out_size;

    wt_kernel<<<256, 256>>>(W_hh);
    xw_kernel<<<1024, 256>>>(data, W_ih, b_ih, b_hh);
    rnn_scan_kernel<<<128, 512>>>(h0);
    attn_kernel<<<2048, 256>>>(nidx, W_lin, b_lin, out);
}